// round 1
// baseline (speedup 1.0000x reference)
#include <cuda_runtime.h>
#include <math.h>

// Shapes (fixed for this problem)
//   B=64, TQ=64, TP=1024, H=A=1024
#define NB  64
#define TQn 64
#define TPn 1024
#define Hn  1024

// ---------------- scratch (__device__ globals: allocation-guard safe) ----------
__device__ float g_PK[67108864];        // 256MB: passage @ Wk_p  (also reused for question@Wk_q)
__device__ float g_sq[NB * TQn];        // question logits
__device__ float g_alpha[NB * TPn];     // softmax weights (q and p reuse)
__device__ float g_hidden[NB * Hn];     // question summary
__device__ float g_inputs[NB * Hn];     // pooled passage
__device__ float g_gout[NB * Hn];       // GRU output state
__device__ float g_Q1[NB * Hn];
__device__ float g_Q2[NB * Hn];
__device__ float g_cq[Hn];              // V_q @ Wq_q
__device__ float g_gi[NB * 3 * Hn];
__device__ float g_gh[NB * 3 * Hn];

// ---------------- SGEMM: C[M,1024] = A[M,1024] @ B[1024,1024], fp32 -----------
// 128x128 block tile, BK=8, 256 threads, 8x8 register tile per thread.
__global__ __launch_bounds__(256) void sgemm_k(const float* __restrict__ A,
                                               const float* __restrict__ B,
                                               float* __restrict__ C) {
    __shared__ float As[8][128];
    __shared__ float Bs[8][128];
    const int tid  = threadIdx.x;
    const int row0 = blockIdx.y * 128;
    const int col0 = blockIdx.x * 128;
    const int tx = tid & 15, ty = tid >> 4;
    const int arow = tid >> 1, acol = (tid & 1) << 2;   // A: 128 rows x 8 k
    const int brow = tid >> 5, bcol = (tid & 31) << 2;  // B: 8 k x 128 cols
    const float* Ap = A + (size_t)(row0 + arow) * 1024 + acol;
    const float* Bp = B + (size_t)brow * 1024 + col0 + bcol;

    float acc[8][8];
#pragma unroll
    for (int i = 0; i < 8; i++)
#pragma unroll
        for (int j = 0; j < 8; j++) acc[i][j] = 0.f;

    for (int k0 = 0; k0 < 1024; k0 += 8) {
        float4 a = *(const float4*)(Ap + k0);
        As[acol + 0][arow] = a.x;
        As[acol + 1][arow] = a.y;
        As[acol + 2][arow] = a.z;
        As[acol + 3][arow] = a.w;
        *(float4*)&Bs[brow][bcol] = *(const float4*)(Bp + (size_t)k0 * 1024);
        __syncthreads();
#pragma unroll
        for (int k = 0; k < 8; k++) {
            float ra[8], rb[8];
#pragma unroll
            for (int i = 0; i < 8; i++) ra[i] = As[k][ty * 8 + i];
#pragma unroll
            for (int j = 0; j < 8; j++) rb[j] = Bs[k][tx * 8 + j];
#pragma unroll
            for (int i = 0; i < 8; i++)
#pragma unroll
                for (int j = 0; j < 8; j++)
                    acc[i][j] = fmaf(ra[i], rb[j], acc[i][j]);
        }
        __syncthreads();
    }
#pragma unroll
    for (int i = 0; i < 8; i++) {
        float* crow = C + (size_t)(row0 + ty * 8 + i) * 1024 + col0 + tx * 8;
        *(float4*)(crow)     = make_float4(acc[i][0], acc[i][1], acc[i][2], acc[i][3]);
        *(float4*)(crow + 4) = make_float4(acc[i][4], acc[i][5], acc[i][6], acc[i][7]);
    }
}

// ---------------- score: s[r] = mask? sum_a w[a]*tanh(C[r,a]+q[..,a]) : -1e30 --
// per_row=0: qterm is a single [1024] vector (c_q). per_row=1: qterm[r>>10, a].
__global__ __launch_bounds__(256) void score_k(const float* __restrict__ C,
                                               const float* __restrict__ qterm,
                                               const float* __restrict__ wv,
                                               const float* __restrict__ mask,
                                               float* __restrict__ outs,
                                               int per_row) {
    const int r = blockIdx.x, tid = threadIdx.x;
    __shared__ float red[8];
    const float* crow = C + (size_t)r * 1024;
    const float* q = per_row ? (qterm + (size_t)(r >> 10) * 1024) : qterm;
    float acc = 0.f;
    for (int c = tid; c < 1024; c += 256)
        acc += wv[c] * tanhf(crow[c] + q[c]);
    for (int o = 16; o; o >>= 1) acc += __shfl_xor_sync(0xffffffffu, acc, o);
    if ((tid & 31) == 0) red[tid >> 5] = acc;
    __syncthreads();
    if (tid == 0) {
        float s = 0.f;
#pragma unroll
        for (int w = 0; w < 8; w++) s += red[w];
        outs[r] = (mask[r] > 0.f) ? s : -1e30f;
    }
}

// ---------------- masked softmax over T per batch row ------------------------
__global__ __launch_bounds__(256) void softmax_k(const float* __restrict__ s,
                                                 float* __restrict__ alpha, int T) {
    const int b = blockIdx.x, tid = threadIdx.x;
    __shared__ float red[8];
    __shared__ float sh;
    const float* sb = s + (size_t)b * T;
    float mx = -3.0e38f;
    for (int t = tid; t < T; t += 256) mx = fmaxf(mx, sb[t]);
    for (int o = 16; o; o >>= 1) mx = fmaxf(mx, __shfl_xor_sync(0xffffffffu, mx, o));
    if ((tid & 31) == 0) red[tid >> 5] = mx;
    __syncthreads();
    if (tid == 0) {
        float v = red[0];
#pragma unroll
        for (int w = 1; w < 8; w++) v = fmaxf(v, red[w]);
        sh = v;
    }
    __syncthreads();
    mx = sh;
    float sum = 0.f;
    for (int t = tid; t < T; t += 256) {
        float e = expf(sb[t] - mx);
        alpha[(size_t)b * T + t] = e;
        sum += e;
    }
    for (int o = 16; o; o >>= 1) sum += __shfl_xor_sync(0xffffffffu, sum, o);
    __syncthreads();
    if ((tid & 31) == 0) red[tid >> 5] = sum;
    __syncthreads();
    if (tid == 0) {
        float v = 0.f;
#pragma unroll
        for (int w = 0; w < 8; w++) v += red[w];
        sh = 1.f / v;
    }
    __syncthreads();
    float inv = sh;
    for (int t = tid; t < T; t += 256) alpha[(size_t)b * T + t] *= inv;
}

// ---------------- pooled[b,h] = sum_t alpha[b,t] * key[b,t,h] -----------------
__global__ __launch_bounds__(256) void pool_k(const float* __restrict__ key,
                                              const float* __restrict__ alpha,
                                              float* __restrict__ out, int T) {
    const int b = blockIdx.x;
    const int h = blockIdx.y * 256 + threadIdx.x;
    const float* kb = key + (size_t)b * T * 1024 + h;
    const float* ab = alpha + (size_t)b * T;
    float a0 = 0.f, a1 = 0.f, a2 = 0.f, a3 = 0.f;
    for (int t = 0; t < T; t += 4) {
        a0 += ab[t + 0] * kb[(size_t)(t + 0) * 1024];
        a1 += ab[t + 1] * kb[(size_t)(t + 1) * 1024];
        a2 += ab[t + 2] * kb[(size_t)(t + 2) * 1024];
        a3 += ab[t + 3] * kb[(size_t)(t + 3) * 1024];
    }
    out[(size_t)b * 1024 + h] = (a0 + a1) + (a2 + a3);
}

// ---------------- out[b,j] = sum_h x[b,h] * W[h,j]   (W row-major [1024,1024]) -
__global__ __launch_bounds__(256) void xw_k(const float* __restrict__ x,
                                            const float* __restrict__ W,
                                            float* __restrict__ out) {
    const int b = blockIdx.y;
    const int j = blockIdx.x * 256 + threadIdx.x;
    __shared__ float xs[1024];
    for (int i = threadIdx.x; i < 1024; i += 256) xs[i] = x[(size_t)b * 1024 + i];
    __syncthreads();
    const float* Wc = W + j;
    float a0 = 0.f, a1 = 0.f, a2 = 0.f, a3 = 0.f;
    for (int h = 0; h < 1024; h += 4) {
        a0 += xs[h + 0] * Wc[(size_t)(h + 0) * 1024];
        a1 += xs[h + 1] * Wc[(size_t)(h + 1) * 1024];
        a2 += xs[h + 2] * Wc[(size_t)(h + 2) * 1024];
        a3 += xs[h + 3] * Wc[(size_t)(h + 3) * 1024];
    }
    out[(size_t)b * 1024 + j] = (a0 + a1) + (a2 + a3);
}

// ---------------- out[b,j] = bias[j] + sum_h x[b,h]*W[j,h]  (torch Linear-style)
__global__ __launch_bounds__(256) void rowdot_k(const float* __restrict__ x,
                                                const float* __restrict__ W,
                                                const float* __restrict__ bias,
                                                float* __restrict__ out, int N) {
    const int b = blockIdx.y;
    const int w = threadIdx.x >> 5, lane = threadIdx.x & 31;
    const int j = blockIdx.x * 8 + w;
    const float* xr = x + (size_t)b * 1024;
    const float* wr = W + (size_t)j * 1024;
    float a0 = 0.f, a1 = 0.f;
    for (int h = lane; h < 1024; h += 64) {
        a0 += xr[h] * wr[h];
        a1 += xr[h + 32] * wr[h + 32];
    }
    float acc = a0 + a1;
    for (int o = 16; o; o >>= 1) acc += __shfl_xor_sync(0xffffffffu, acc, o);
    if (!lane) out[(size_t)b * N + j] = acc + bias[j];
}

// ---------------- GRU cell combine (torch.nn.GRUCell math) --------------------
__global__ __launch_bounds__(256) void gru_k() {
    const int i = blockIdx.x * 256 + threadIdx.x;  // NB*Hn = 65536
    const int b = i >> 10, h = i & 1023;
    const float* gi = g_gi + (size_t)b * 3072;
    const float* gh = g_gh + (size_t)b * 3072;
    float r = 1.f / (1.f + expf(-(gi[h] + gh[h])));
    float z = 1.f / (1.f + expf(-(gi[1024 + h] + gh[1024 + h])));
    float n = tanhf(gi[2048 + h] + r * gh[2048 + h]);
    g_gout[i] = (1.f - z) * n + z * g_hidden[i];
}

// ---------------- launch ------------------------------------------------------
extern "C" void kernel_launch(void* const* d_in, const int* in_sizes, int n_in,
                              void* d_out, int out_size) {
    const float* question = (const float*)d_in[0];   // [64,64,1024]
    const float* qmask    = (const float*)d_in[1];   // [64,64]
    const float* passage  = (const float*)d_in[2];   // [64,1024,1024]
    const float* pmask    = (const float*)d_in[3];   // [64,1024]
    const float* Vq       = (const float*)d_in[4];   // [1,1,1024]
    const float* Wk_q     = (const float*)d_in[5];   // [1024,1024]
    const float* Wq_q     = (const float*)d_in[6];
    const float* w_q      = (const float*)d_in[7];   // [1024]
    const float* Wk_p     = (const float*)d_in[8];
    const float* Wq_p     = (const float*)d_in[9];
    const float* w_p      = (const float*)d_in[10];
    const float* W_ih     = (const float*)d_in[11];  // [3072,1024]
    const float* W_hh     = (const float*)d_in[12];
    const float* b_ih     = (const float*)d_in[13];
    const float* b_hh     = (const float*)d_in[14];
    float* out = (float*)d_out;                      // [2*64*1024] = begin|end

    float *pPK, *psq, *palpha, *phid, *pinp, *pgout, *pQ1, *pQ2, *pcq, *pgi, *pgh;
    cudaGetSymbolAddress((void**)&pPK,    g_PK);
    cudaGetSymbolAddress((void**)&psq,    g_sq);
    cudaGetSymbolAddress((void**)&palpha, g_alpha);
    cudaGetSymbolAddress((void**)&phid,   g_hidden);
    cudaGetSymbolAddress((void**)&pinp,   g_inputs);
    cudaGetSymbolAddress((void**)&pgout,  g_gout);
    cudaGetSymbolAddress((void**)&pQ1,    g_Q1);
    cudaGetSymbolAddress((void**)&pQ2,    g_Q2);
    cudaGetSymbolAddress((void**)&pcq,    g_cq);
    cudaGetSymbolAddress((void**)&pgi,    g_gi);
    cudaGetSymbolAddress((void**)&pgh,    g_gh);

    // 1. c_q = V_q @ Wq_q                        [1024]
    xw_k<<<dim3(4, 1), 256>>>(Vq, Wq_q, pcq);
    // 2. QK = question @ Wk_q  (PK scratch reused, M=4096)
    sgemm_k<<<dim3(8, 32), 256>>>(question, Wk_q, pPK);
    // 3. question logits (masked)
    score_k<<<4096, 256>>>(pPK, pcq, w_q, qmask, psq, 0);
    // 4-5. softmax over TQ + pool -> hidden
    softmax_k<<<64, 256>>>(psq, palpha, 64);
    pool_k<<<dim3(64, 4), 256>>>(question, palpha, phid, 64);
    // 6. Q1 = hidden @ Wq_p
    xw_k<<<dim3(4, 64), 256>>>(phid, Wq_p, pQ1);
    // 7. PK = passage @ Wk_p   (M=65536 — dominant GEMM, computed ONCE)
    sgemm_k<<<dim3(8, 512), 256>>>(passage, Wk_p, pPK);
    // 8. ans_begin = masked logits -> first half of output
    score_k<<<65536, 256>>>(pPK, pQ1, w_p, pmask, out, 1);
    // 9-10. softmax over TP + pool -> inputs
    softmax_k<<<64, 256>>>(out, palpha, 1024);
    pool_k<<<dim3(64, 4), 256>>>(passage, palpha, pinp, 1024);
    // 11. GRU: gi = inputs@W_ih^T + b_ih ; gh = hidden@W_hh^T + b_hh ; combine
    rowdot_k<<<dim3(384, 64), 256>>>(pinp, W_ih, b_ih, pgi, 3072);
    rowdot_k<<<dim3(384, 64), 256>>>(phid, W_hh, b_hh, pgh, 3072);
    gru_k<<<256, 256>>>();
    // 12. Q2 = gru_out @ Wq_p
    xw_k<<<dim3(4, 64), 256>>>(pgout, Wq_p, pQ2);
    // 13. ans_end from stored PK -> second half of output
    score_k<<<65536, 256>>>(pPK, pQ2, w_p, pmask, out + 65536, 1);
}

// round 2
// speedup vs baseline: 2.1131x; 2.1131x over previous
#include <cuda_runtime.h>
#include <cuda_bf16.h>
#include <math.h>
#include <stdint.h>

// Shapes (fixed): B=64, TQ=64, TP=1024, H=A=1024
#define NB  64
#define TQn 64
#define TPn 1024
#define Hn  1024

// ---------------- scratch (__device__ globals: allocation-guard safe) ----------
__device__ float g_PK[67108864];        // 256MB: passage @ Wk_p (reused for question@Wk_q)
__device__ float g_sq[NB * TQn];
__device__ float g_alpha[NB * TPn];
__device__ float g_hidden[NB * Hn];
__device__ float g_inputs[NB * Hn];
__device__ float g_gout[NB * Hn];
__device__ float g_Q1[NB * Hn];
__device__ float g_Q2[NB * Hn];
__device__ float g_cq[Hn];
__device__ float g_gi[NB * 3 * Hn];
__device__ float g_gh[NB * 3 * Hn];

// ---------------- fast tanh: 1 - 2/(exp(2x)+1), MUFU-based ---------------------
__device__ __forceinline__ float fast_tanh(float x) {
    float e = __expf(fminf(2.0f * x, 80.0f));
    return 1.0f - __fdividef(2.0f, e + 1.0f);
}

// ---------------- mma.sync helpers --------------------------------------------
__device__ __forceinline__ void ldsm_x4(uint32_t* r, const void* p) {
    uint32_t a = (uint32_t)__cvta_generic_to_shared(p);
    asm volatile("ldmatrix.sync.aligned.m8n8.x4.shared.b16 {%0,%1,%2,%3}, [%4];"
                 : "=r"(r[0]), "=r"(r[1]), "=r"(r[2]), "=r"(r[3]) : "r"(a));
}
__device__ __forceinline__ void ldsm_x4_t(uint32_t* r, const void* p) {
    uint32_t a = (uint32_t)__cvta_generic_to_shared(p);
    asm volatile("ldmatrix.sync.aligned.m8n8.x4.trans.shared.b16 {%0,%1,%2,%3}, [%4];"
                 : "=r"(r[0]), "=r"(r[1]), "=r"(r[2]), "=r"(r[3]) : "r"(a));
}
__device__ __forceinline__ void mma_bf16(float* d, const uint32_t* a, const uint32_t* b) {
    asm volatile(
        "mma.sync.aligned.m16n8k16.row.col.f32.bf16.bf16.f32 "
        "{%0,%1,%2,%3}, {%4,%5,%6,%7}, {%8,%9}, {%0,%1,%2,%3};"
        : "+f"(d[0]), "+f"(d[1]), "+f"(d[2]), "+f"(d[3])
        : "r"(a[0]), "r"(a[1]), "r"(a[2]), "r"(a[3]), "r"(b[0]), "r"(b[1]));
}

// ---------------- split-bf16 tensor-core GEMM ----------------------------------
// C[M,1024] = A[M,1024] @ B[1024,1024], fp32 in/out, bf16 hi+lo 3-pass (hh+hl+lh).
// CTA tile 128x128, K-chunk 32. 8 warps as 2(M)x4(N), warp tile 64x32.
#define AST 40    // A smem row stride in halves (conflict-free for ldmatrix)
#define BST 136   // B smem row stride in halves
__global__ __launch_bounds__(256) void mma_gemm_k(const float* __restrict__ A,
                                                  const float* __restrict__ B,
                                                  float* __restrict__ C) {
    __shared__ __nv_bfloat16 sAh[128 * AST];
    __shared__ __nv_bfloat16 sAl[128 * AST];
    __shared__ __nv_bfloat16 sBh[32 * BST];
    __shared__ __nv_bfloat16 sBl[32 * BST];

    const int tid = threadIdx.x;
    const int warp = tid >> 5, lane = tid & 31;
    const int wm = warp >> 2, wn = warp & 3;           // 2 x 4 warp grid
    const int row0 = blockIdx.y * 128, col0 = blockIdx.x * 128;

    float acc[4][4][4];
#pragma unroll
    for (int i = 0; i < 4; i++)
#pragma unroll
        for (int j = 0; j < 4; j++)
#pragma unroll
            for (int v = 0; v < 4; v++) acc[i][j][v] = 0.f;

    for (int k0 = 0; k0 < 1024; k0 += 32) {
        // ---- load + split-convert A tile (128x32 fp32) ----
#pragma unroll
        for (int j = 0; j < 4; j++) {
            int idx = tid + j * 256;                 // 1024 float4s
            int r = idx >> 3, c = (idx & 7) << 2;
            float4 v = *(const float4*)(A + (size_t)(row0 + r) * 1024 + k0 + c);
            __nv_bfloat16 hx = __float2bfloat16(v.x), hy = __float2bfloat16(v.y);
            __nv_bfloat16 hz = __float2bfloat16(v.z), hw = __float2bfloat16(v.w);
            __nv_bfloat16 lx = __float2bfloat16(v.x - __bfloat162float(hx));
            __nv_bfloat16 ly = __float2bfloat16(v.y - __bfloat162float(hy));
            __nv_bfloat16 lz = __float2bfloat16(v.z - __bfloat162float(hz));
            __nv_bfloat16 lw = __float2bfloat16(v.w - __bfloat162float(hw));
            int o = r * AST + c;
            *(__nv_bfloat162*)&sAh[o]     = __halves2bfloat162(hx, hy);
            *(__nv_bfloat162*)&sAh[o + 2] = __halves2bfloat162(hz, hw);
            *(__nv_bfloat162*)&sAl[o]     = __halves2bfloat162(lx, ly);
            *(__nv_bfloat162*)&sAl[o + 2] = __halves2bfloat162(lz, lw);
        }
        // ---- load + split-convert B tile (32x128 fp32) ----
#pragma unroll
        for (int j = 0; j < 4; j++) {
            int idx = tid + j * 256;
            int r = idx >> 5, c = (idx & 31) << 2;
            float4 v = *(const float4*)(B + (size_t)(k0 + r) * 1024 + col0 + c);
            __nv_bfloat16 hx = __float2bfloat16(v.x), hy = __float2bfloat16(v.y);
            __nv_bfloat16 hz = __float2bfloat16(v.z), hw = __float2bfloat16(v.w);
            __nv_bfloat16 lx = __float2bfloat16(v.x - __bfloat162float(hx));
            __nv_bfloat16 ly = __float2bfloat16(v.y - __bfloat162float(hy));
            __nv_bfloat16 lz = __float2bfloat16(v.z - __bfloat162float(hz));
            __nv_bfloat16 lw = __float2bfloat16(v.w - __bfloat162float(hw));
            int o = r * BST + c;
            *(__nv_bfloat162*)&sBh[o]     = __halves2bfloat162(hx, hy);
            *(__nv_bfloat162*)&sBh[o + 2] = __halves2bfloat162(hz, hw);
            *(__nv_bfloat162*)&sBl[o]     = __halves2bfloat162(lx, ly);
            *(__nv_bfloat162*)&sBl[o + 2] = __halves2bfloat162(lz, lw);
        }
        __syncthreads();

#pragma unroll
        for (int kk = 0; kk < 32; kk += 16) {
            uint32_t ah[4][4], al[4][4], bh[2][4], bl[2][4];
            int arow = (lane & 15), acb = kk + ((lane >> 4) << 3);
#pragma unroll
            for (int mi = 0; mi < 4; mi++) {
                const __nv_bfloat16* pa = &sAh[(wm * 64 + mi * 16 + arow) * AST + acb];
                ldsm_x4(ah[mi], pa);
                const __nv_bfloat16* pl = &sAl[(wm * 64 + mi * 16 + arow) * AST + acb];
                ldsm_x4(al[mi], pl);
            }
            int bkr = kk + (lane & 15), bcb = wn * 32 + ((lane >> 4) << 3);
#pragma unroll
            for (int ni = 0; ni < 2; ni++) {
                const __nv_bfloat16* pb = &sBh[bkr * BST + bcb + ni * 16];
                ldsm_x4_t(bh[ni], pb);
                const __nv_bfloat16* pbl = &sBl[bkr * BST + bcb + ni * 16];
                ldsm_x4_t(bl[ni], pbl);
            }
#pragma unroll
            for (int mi = 0; mi < 4; mi++)
#pragma unroll
                for (int nj = 0; nj < 4; nj++) {
                    int ni = nj >> 1, p = (nj & 1) * 2;
                    mma_bf16(acc[mi][nj], ah[mi], &bh[ni][p]);   // hi*hi
                    mma_bf16(acc[mi][nj], ah[mi], &bl[ni][p]);   // hi*lo
                    mma_bf16(acc[mi][nj], al[mi], &bh[ni][p]);   // lo*hi
                }
        }
        __syncthreads();
    }

    // ---- epilogue: store fp32 C ----
    const int rbase = row0 + wm * 64, cbase = col0 + wn * 32;
    const int lr = lane >> 2, lc = (lane & 3) * 2;
#pragma unroll
    for (int mi = 0; mi < 4; mi++)
#pragma unroll
        for (int nj = 0; nj < 4; nj++) {
            int rr = rbase + mi * 16 + lr;
            int cc = cbase + nj * 8 + lc;
            *(float2*)&C[(size_t)rr * 1024 + cc] =
                make_float2(acc[mi][nj][0], acc[mi][nj][1]);
            *(float2*)&C[(size_t)(rr + 8) * 1024 + cc] =
                make_float2(acc[mi][nj][2], acc[mi][nj][3]);
        }
}

// ---------------- score: s[r] = mask? sum_a w[a]*tanh(C[r,a]+q[..,a]) : -1e30 --
__global__ __launch_bounds__(256) void score_k(const float* __restrict__ C,
                                               const float* __restrict__ qterm,
                                               const float* __restrict__ wv,
                                               const float* __restrict__ mask,
                                               float* __restrict__ outs,
                                               int per_row) {
    const int r = blockIdx.x, tid = threadIdx.x;
    __shared__ float red[8];
    const float* crow = C + (size_t)r * 1024;
    const float* q = per_row ? (qterm + (size_t)(r >> 10) * 1024) : qterm;
    float acc = 0.f;
    for (int c = tid; c < 1024; c += 256)
        acc += wv[c] * fast_tanh(crow[c] + q[c]);
    for (int o = 16; o; o >>= 1) acc += __shfl_xor_sync(0xffffffffu, acc, o);
    if ((tid & 31) == 0) red[tid >> 5] = acc;
    __syncthreads();
    if (tid == 0) {
        float s = 0.f;
#pragma unroll
        for (int w = 0; w < 8; w++) s += red[w];
        outs[r] = (mask[r] > 0.f) ? s : -1e30f;
    }
}

// ---------------- masked softmax over T per batch row ------------------------
__global__ __launch_bounds__(256) void softmax_k(const float* __restrict__ s,
                                                 float* __restrict__ alpha, int T) {
    const int b = blockIdx.x, tid = threadIdx.x;
    __shared__ float red[8];
    __shared__ float sh;
    const float* sb = s + (size_t)b * T;
    float mx = -3.0e38f;
    for (int t = tid; t < T; t += 256) mx = fmaxf(mx, sb[t]);
    for (int o = 16; o; o >>= 1) mx = fmaxf(mx, __shfl_xor_sync(0xffffffffu, mx, o));
    if ((tid & 31) == 0) red[tid >> 5] = mx;
    __syncthreads();
    if (tid == 0) {
        float v = red[0];
#pragma unroll
        for (int w = 1; w < 8; w++) v = fmaxf(v, red[w]);
        sh = v;
    }
    __syncthreads();
    mx = sh;
    float sum = 0.f;
    for (int t = tid; t < T; t += 256) {
        float e = expf(sb[t] - mx);
        alpha[(size_t)b * T + t] = e;
        sum += e;
    }
    for (int o = 16; o; o >>= 1) sum += __shfl_xor_sync(0xffffffffu, sum, o);
    __syncthreads();
    if ((tid & 31) == 0) red[tid >> 5] = sum;
    __syncthreads();
    if (tid == 0) {
        float v = 0.f;
#pragma unroll
        for (int w = 0; w < 8; w++) v += red[w];
        sh = 1.f / v;
    }
    __syncthreads();
    float inv = sh;
    for (int t = tid; t < T; t += 256) alpha[(size_t)b * T + t] *= inv;
}

// ---------------- pooled[b,h] = sum_t alpha[b,t] * key[b,t,h] -----------------
__global__ __launch_bounds__(256) void pool_k(const float* __restrict__ key,
                                              const float* __restrict__ alpha,
                                              float* __restrict__ out, int T) {
    const int b = blockIdx.x;
    const int h = blockIdx.y * 256 + threadIdx.x;
    const float* kb = key + (size_t)b * T * 1024 + h;
    const float* ab = alpha + (size_t)b * T;
    float a0 = 0.f, a1 = 0.f, a2 = 0.f, a3 = 0.f;
    for (int t = 0; t < T; t += 4) {
        a0 += ab[t + 0] * kb[(size_t)(t + 0) * 1024];
        a1 += ab[t + 1] * kb[(size_t)(t + 1) * 1024];
        a2 += ab[t + 2] * kb[(size_t)(t + 2) * 1024];
        a3 += ab[t + 3] * kb[(size_t)(t + 3) * 1024];
    }
    out[(size_t)b * 1024 + h] = (a0 + a1) + (a2 + a3);
}

// ---------------- out[b,j] = sum_h x[b,h] * W[h,j]   (W row-major) ------------
__global__ __launch_bounds__(256) void xw_k(const float* __restrict__ x,
                                            const float* __restrict__ W,
                                            float* __restrict__ out) {
    const int b = blockIdx.y;
    const int j = blockIdx.x * 256 + threadIdx.x;
    __shared__ float xs[1024];
    for (int i = threadIdx.x; i < 1024; i += 256) xs[i] = x[(size_t)b * 1024 + i];
    __syncthreads();
    const float* Wc = W + j;
    float a0 = 0.f, a1 = 0.f, a2 = 0.f, a3 = 0.f;
    for (int h = 0; h < 1024; h += 4) {
        a0 += xs[h + 0] * Wc[(size_t)(h + 0) * 1024];
        a1 += xs[h + 1] * Wc[(size_t)(h + 1) * 1024];
        a2 += xs[h + 2] * Wc[(size_t)(h + 2) * 1024];
        a3 += xs[h + 3] * Wc[(size_t)(h + 3) * 1024];
    }
    out[(size_t)b * 1024 + j] = (a0 + a1) + (a2 + a3);
}

// ---------------- out[b,j] = bias[j] + sum_h x[b,h]*W[j,h] --------------------
__global__ __launch_bounds__(256) void rowdot_k(const float* __restrict__ x,
                                                const float* __restrict__ W,
                                                const float* __restrict__ bias,
                                                float* __restrict__ out, int N) {
    const int b = blockIdx.y;
    const int w = threadIdx.x >> 5, lane = threadIdx.x & 31;
    const int j = blockIdx.x * 8 + w;
    const float* xr = x + (size_t)b * 1024;
    const float* wr = W + (size_t)j * 1024;
    float a0 = 0.f, a1 = 0.f;
    for (int h = lane; h < 1024; h += 64) {
        a0 += xr[h] * wr[h];
        a1 += xr[h + 32] * wr[h + 32];
    }
    float acc = a0 + a1;
    for (int o = 16; o; o >>= 1) acc += __shfl_xor_sync(0xffffffffu, acc, o);
    if (!lane) out[(size_t)b * N + j] = acc + bias[j];
}

// ---------------- GRU cell combine --------------------------------------------
__global__ __launch_bounds__(256) void gru_k() {
    const int i = blockIdx.x * 256 + threadIdx.x;
    const int b = i >> 10, h = i & 1023;
    const float* gi = g_gi + (size_t)b * 3072;
    const float* gh = g_gh + (size_t)b * 3072;
    float r = 1.f / (1.f + expf(-(gi[h] + gh[h])));
    float z = 1.f / (1.f + expf(-(gi[1024 + h] + gh[1024 + h])));
    float n = tanhf(gi[2048 + h] + r * gh[2048 + h]);
    g_gout[i] = (1.f - z) * n + z * g_hidden[i];
}

// ---------------- launch ------------------------------------------------------
extern "C" void kernel_launch(void* const* d_in, const int* in_sizes, int n_in,
                              void* d_out, int out_size) {
    const float* question = (const float*)d_in[0];
    const float* qmask    = (const float*)d_in[1];
    const float* passage  = (const float*)d_in[2];
    const float* pmask    = (const float*)d_in[3];
    const float* Vq       = (const float*)d_in[4];
    const float* Wk_q     = (const float*)d_in[5];
    const float* Wq_q     = (const float*)d_in[6];
    const float* w_q      = (const float*)d_in[7];
    const float* Wk_p     = (const float*)d_in[8];
    const float* Wq_p     = (const float*)d_in[9];
    const float* w_p      = (const float*)d_in[10];
    const float* W_ih     = (const float*)d_in[11];
    const float* W_hh     = (const float*)d_in[12];
    const float* b_ih     = (const float*)d_in[13];
    const float* b_hh     = (const float*)d_in[14];
    float* out = (float*)d_out;

    float *pPK, *psq, *palpha, *phid, *pinp, *pgout, *pQ1, *pQ2, *pcq, *pgi, *pgh;
    cudaGetSymbolAddress((void**)&pPK,    g_PK);
    cudaGetSymbolAddress((void**)&psq,    g_sq);
    cudaGetSymbolAddress((void**)&palpha, g_alpha);
    cudaGetSymbolAddress((void**)&phid,   g_hidden);
    cudaGetSymbolAddress((void**)&pinp,   g_inputs);
    cudaGetSymbolAddress((void**)&pgout,  g_gout);
    cudaGetSymbolAddress((void**)&pQ1,    g_Q1);
    cudaGetSymbolAddress((void**)&pQ2,    g_Q2);
    cudaGetSymbolAddress((void**)&pcq,    g_cq);
    cudaGetSymbolAddress((void**)&pgi,    g_gi);
    cudaGetSymbolAddress((void**)&pgh,    g_gh);

    // 1. c_q = V_q @ Wq_q
    xw_k<<<dim3(4, 1), 256>>>(Vq, Wq_q, pcq);
    // 2. QK = question @ Wk_q  (M=4096, tensor-core)
    mma_gemm_k<<<dim3(8, 32), 256>>>(question, Wk_q, pPK);
    // 3. question logits
    score_k<<<4096, 256>>>(pPK, pcq, w_q, qmask, psq, 0);
    // 4-5. softmax + pool -> hidden
    softmax_k<<<64, 256>>>(psq, palpha, 64);
    pool_k<<<dim3(64, 4), 256>>>(question, palpha, phid, 64);
    // 6. Q1 = hidden @ Wq_p
    xw_k<<<dim3(4, 64), 256>>>(phid, Wq_p, pQ1);
    // 7. PK = passage @ Wk_p  (M=65536, tensor-core, computed ONCE)
    mma_gemm_k<<<dim3(8, 512), 256>>>(passage, Wk_p, pPK);
    // 8. ans_begin
    score_k<<<65536, 256>>>(pPK, pQ1, w_p, pmask, out, 1);
    // 9-10. softmax + pool -> inputs
    softmax_k<<<64, 256>>>(out, palpha, 1024);
    pool_k<<<dim3(64, 4), 256>>>(passage, palpha, pinp, 1024);
    // 11. GRU
    rowdot_k<<<dim3(384, 64), 256>>>(pinp, W_ih, b_ih, pgi, 3072);
    rowdot_k<<<dim3(384, 64), 256>>>(phid, W_hh, b_hh, pgh, 3072);
    gru_k<<<256, 256>>>();
    // 12. Q2 = gru_out @ Wq_p
    xw_k<<<dim3(4, 64), 256>>>(pgout, Wq_p, pQ2);
    // 13. ans_end
    score_k<<<65536, 256>>>(pPK, pQ2, w_p, pmask, out + 65536, 1);
}